// round 9
// baseline (speedup 1.0000x reference)
#include <cuda_runtime.h>
#include <cuda_fp16.h>
#include <cstdint>

// Problem constants
#define N_TOK 16384
#define C_DIM 2048
#define E_DIM 64
#define CAP   640                 // int(1.25 * 16384 * 2 / 64)

#define TOK_CTA   128             // tokens per k_main CTA
#define NCTA_MAIN (N_TOK / TOK_CTA)   // 128
#define KT        32              // K-tile (2 x k16 mma steps)
#define NTILE     (C_DIM / KT)    // 64
#define NBLK64    256             // 64-token blocks (rank/scan granularity)
#define NTHREADS  512

#define XSTR 40                   // xs row stride (floats)
#define BSTR 40                   // W tile row stride (halves)
#define GSTR 66                   // logits row stride (floats)

#define XS_BYTES (TOK_CTA * XSTR * 4)     // 20480
#define WH_BYTES (E_DIM * BSTR * 2)       // 5120
#define STAGE_B  (XS_BYTES + 2 * WH_BYTES)    // 30720
#define SMEM_DYN (2 * STAGE_B)                // 61440

#define INV1024 0.0009765625f

// Output layout (float32)
#define DISP_OFF  ((size_t)0)
#define COMB_OFF  ((size_t)N_TOK * E_DIM * 2)
#define AUX_OFF   ((size_t)2 * N_TOK * E_DIM * 2)
#define Z_OFF     (AUX_OFF + 1)

// ---------------- scratch (static device globals; no allocs) ----------------
__device__ __half   g_Whh[E_DIM * C_DIM];   // fp16 hi part of W [e][k]
__device__ __half   g_Whl[E_DIM * C_DIM];   // fp16 (lo part * 1024)
__device__ uint32_t g_t2i[N_TOK];           // e1 | e2<<8
__device__ float2   g_t2v[N_TOK];           // top2 gate values
__device__ uint32_t g_rank[N_TOK];          // local rank: r0 | r1<<16
__device__ int      g_counts[NBLK64 * 128]; // per-64tok-block bin counts
__device__ int      g_off[NBLK64 * 128];    // exclusive scan across blocks
__device__ float    g_mepart[NCTA_MAIN * E_DIM];
__device__ float    g_zpart[NCTA_MAIN];

// ---------------- helpers ----------------
__device__ __forceinline__ uint32_t smem_u32(const void* p) {
    return (uint32_t)__cvta_generic_to_shared(p);
}
__device__ __forceinline__ void cpa16(uint32_t dst, const void* src) {
    asm volatile("cp.async.cg.shared.global [%0], [%1], 16;"
                 :: "r"(dst), "l"(src) : "memory");
}
__device__ __forceinline__ void mma16(float* d,
                                      uint32_t a0, uint32_t a1, uint32_t a2, uint32_t a3,
                                      uint32_t b0, uint32_t b1) {
    asm volatile(
        "mma.sync.aligned.m16n8k16.row.col.f32.f16.f16.f32 "
        "{%0,%1,%2,%3}, {%4,%5,%6,%7}, {%8,%9}, {%0,%1,%2,%3};"
        : "+f"(d[0]), "+f"(d[1]), "+f"(d[2]), "+f"(d[3])
        : "r"(a0), "r"(a1), "r"(a2), "r"(a3), "r"(b0), "r"(b1));
}
__device__ __forceinline__ void split2(float2 v, uint32_t& h, uint32_t& l) {
    __half2 hh = __floats2half2_rn(v.x, v.y);
    float2 hf = __half22float2(hh);
    __half2 ll = __floats2half2_rn(v.x - hf.x, v.y - hf.y);
    h = *(uint32_t*)&hh;
    l = *(uint32_t*)&ll;
}

// ---------------- K0: split W into fp16 hi / (lo*1024) ----------------
__global__ __launch_bounds__(256) void k_wsplit(const float* __restrict__ W) {
    int idx = blockIdx.x * 256 + threadIdx.x;   // 131072
    float v = W[idx];
    __half h = __float2half_rn(v);
    g_Whh[idx] = h;
    g_Whl[idx] = __float2half_rn((v - __half2float(h)) * 1024.0f);
}

// ---------------- K1: mma.sync fp16-split GEMM + softmax + top2 + ranks ----
// 512 threads (16 warps, 4/SMSP). Warp w: tokens [(w>>1)*16, +16),
// experts [(w&1)*32, +32) -> 4 n-tiles of m16n8k16.
// accM = (xh+xl)*wh, accL = xh*(wl*1024); logit = accM + accL/1024.
__global__ __launch_bounds__(NTHREADS) void k_main(const float* __restrict__ x) {
    extern __shared__ __align__(16) char smc[];
    __shared__ int   cnt[512];          // [half][warp_in_half][128 bins]
    __shared__ float sinv_s[TOK_CTA];
    __shared__ float redz[4];

    const int tid  = threadIdx.x;
    const int lane = tid & 31;
    const int w    = tid >> 5;
    const int cta  = blockIdx.x;
    const uint32_t smb = smem_u32(smc);
    const float* xbase = x + (size_t)cta * TOK_CTA * C_DIM;

#define LOAD_TILE(t) do {                                                     \
    uint32_t sb_ = smb + ((t) & 1) * STAGE_B;                                 \
    const float* xs_ = xbase + (t) * KT;                                      \
    _Pragma("unroll")                                                         \
    for (int c = tid; c < 1024; c += NTHREADS) {                              \
        int row_ = c >> 3, seg_ = c & 7;                                      \
        cpa16(sb_ + (uint32_t)(row_ * (XSTR * 4) + seg_ * 16),                \
              xs_ + (size_t)row_ * C_DIM + seg_ * 4);                         \
    }                                                                         \
    {                                                                         \
        int r2_ = (tid & 255) >> 2, seg_ = tid & 3;                           \
        const __half* wsrc_ = (tid < 256 ? g_Whh : g_Whl)                     \
            + (size_t)r2_ * C_DIM + (t) * KT + seg_ * 8;                      \
        uint32_t wdst_ = sb_ + XS_BYTES + (tid < 256 ? 0u : (uint32_t)WH_BYTES)\
            + (uint32_t)(r2_ * (BSTR * 2) + seg_ * 16);                       \
        cpa16(wdst_, wsrc_);                                                  \
    }                                                                         \
} while (0)

    float accM[4][4], accL[4][4];
#pragma unroll
    for (int j = 0; j < 4; j++)
#pragma unroll
        for (int q = 0; q < 4; q++) { accM[j][q] = 0.f; accL[j][q] = 0.f; }

    const int tb = (w >> 1) * 16;       // token base
    const int eb = (w & 1) * 32;        // expert base
    const int tr = lane >> 2, tc = lane & 3;

    LOAD_TILE(0);
    asm volatile("cp.async.commit_group;" ::: "memory");

    for (int t = 0; t < NTILE; t++) {
        if (t + 1 < NTILE) LOAD_TILE(t + 1);
        asm volatile("cp.async.commit_group;" ::: "memory");
        asm volatile("cp.async.wait_group 1;" ::: "memory");
        __syncthreads();

        const char* st = smc + (t & 1) * STAGE_B;
        const float* xsA = (const float*)st + (tb + tr) * XSTR + 2 * tc;
        const __half* whB = (const __half*)(st + XS_BYTES) + (eb + tr) * BSTR + 2 * tc;
        const __half* wlB = (const __half*)(st + XS_BYTES + WH_BYTES) + (eb + tr) * BSTR + 2 * tc;

#pragma unroll
        for (int kk = 0; kk < KT; kk += 16) {
            float2 v0 = *(const float2*)(xsA + kk);
            float2 v1 = *(const float2*)(xsA + 8 * XSTR + kk);
            float2 v2 = *(const float2*)(xsA + kk + 8);
            float2 v3 = *(const float2*)(xsA + 8 * XSTR + kk + 8);
            uint32_t ah0, al0, ah1, al1, ah2, al2, ah3, al3;
            split2(v0, ah0, al0);
            split2(v1, ah1, al1);
            split2(v2, ah2, al2);
            split2(v3, ah3, al3);

#pragma unroll
            for (int j = 0; j < 4; j++) {
                const __half* whj = whB + j * 8 * BSTR + kk;
                const __half* wlj = wlB + j * 8 * BSTR + kk;
                uint32_t bh0 = *(const uint32_t*)whj;
                uint32_t bh1 = *(const uint32_t*)(whj + 8);
                uint32_t bl0 = *(const uint32_t*)wlj;
                uint32_t bl1 = *(const uint32_t*)(wlj + 8);
                mma16(accM[j], ah0, ah1, ah2, ah3, bh0, bh1);
                mma16(accM[j], al0, al1, al2, al3, bh0, bh1);
                mma16(accL[j], ah0, ah1, ah2, ah3, bl0, bl1);
            }
        }
        __syncthreads();   // protect buffer t&1 before iter t+1 prefetches t+2
    }

    // ---- combine + store logits to smem (stage0 reuse), stride GSTR ----
    float* gsm = (float*)smc;
    __syncthreads();
#pragma unroll
    for (int j = 0; j < 4; j++) {
        float l0 = accM[j][0] + accL[j][0] * INV1024;
        float l1 = accM[j][1] + accL[j][1] * INV1024;
        float l2 = accM[j][2] + accL[j][2] * INV1024;
        float l3 = accM[j][3] + accL[j][3] * INV1024;
        *(float2*)(gsm + (tb + tr) * GSTR + eb + j * 8 + tc * 2) = make_float2(l0, l1);
        *(float2*)(gsm + (tb + tr + 8) * GSTR + eb + j * 8 + tc * 2) = make_float2(l2, l3);
    }
    cnt[tid & 511] = 0;
    __syncthreads();

    // ---- per-token softmax + top2 (threads 0..127, one token each) ----
    int i1 = 0, i2 = 0, r0 = 0, r1 = 0;
    float zsum = 0.f;
    if (w < 4) {
        float* row = gsm + tid * GSTR;
        float m = row[0];
#pragma unroll 4
        for (int e = 1; e < E_DIM; e++) m = fmaxf(m, row[e]);
        float s = 0.f, b1 = -1.f, b2 = -1.f;
#pragma unroll 4
        for (int e = 0; e < E_DIM; e++) {
            float l = row[e];
            zsum += l * l;
            float v = expf(l - m);
            row[e] = v;            // overwrite with unnormalized gate
            s += v;
            if (v > b1)      { b2 = b1; i2 = i1; b1 = v; i1 = e; }
            else if (v > b2) { b2 = v; i2 = e; }
        }
        float sinv = 1.f / s;
        sinv_s[tid] = sinv;
        int n = cta * TOK_CTA + tid;
        g_t2v[n] = make_float2(b1 * sinv, b2 * sinv);

        // deterministic local ranks (token order) within each 64-token half
        int half = w >> 1, wih = w & 1;
        unsigned lt = (1u << lane) - 1u;
        unsigned m0 = __match_any_sync(0xffffffffu, i1);
        r0 = __popc(m0 & lt);
        if ((m0 & lt) == 0) cnt[half * 256 + wih * 128 + i1] = __popc(m0);
        unsigned m1 = __match_any_sync(0xffffffffu, i2);
        r1 = __popc(m1 & lt);
        if ((m1 & lt) == 0) cnt[half * 256 + wih * 128 + 64 + i2] = __popc(m1);
    }
    // z reduce (warps 4..15 contribute zeros)
#pragma unroll
    for (int o = 16; o > 0; o >>= 1) zsum += __shfl_xor_sync(0xffffffffu, zsum, o);
    if (w < 4 && lane == 0) redz[w] = zsum;
    __syncthreads();

    if (w < 4) {
        int half = w >> 1;
        if ((w & 1) == 1) {               // second warp of half adds first warp's counts
            r0 += cnt[half * 256 + i1];
            r1 += cnt[half * 256 + 64 + i2];
        }
        int n = cta * TOK_CTA + tid;
        g_rank[n] = (uint32_t)r0 | ((uint32_t)r1 << 16);
        g_t2i[n]  = (uint32_t)i1 | ((uint32_t)i2 << 8);
    }
    if (tid < 256) {   // per-64tok-block bin counts (2 halves x 128 bins)
        int half = tid >> 7, b = tid & 127;
        g_counts[(cta * 2 + half) * 128 + b] =
            cnt[half * 256 + b] + cnt[half * 256 + 128 + b];
    }
    if (tid < 64) {
        float sme = 0.f;
        for (int tok = 0; tok < TOK_CTA; tok++)
            sme += gsm[tok * GSTR + tid] * sinv_s[tok];
        g_mepart[cta * 64 + tid] = sme;
    }
    if (tid == 0)
        g_zpart[cta] = redz[0] + redz[1] + redz[2] + redz[3];
#undef LOAD_TILE
}

// ---------------- K2: per-bin scan (blocks 0..127) + losses (block 128) ----
__global__ __launch_bounds__(256) void k_scan(float* __restrict__ out) {
    const int t = threadIdx.x;
    __shared__ int   ired[256];
    __shared__ float fred[256];

    if (blockIdx.x < 128) {
        const int b = blockIdx.x;      // bin
        __shared__ int wsum[8];
        __shared__ int woff[8];
        int c = g_counts[t * 128 + b];
        int v = c;
#pragma unroll
        for (int d = 1; d < 32; d <<= 1) {
            int u = __shfl_up_sync(0xffffffffu, v, d);
            if ((t & 31) >= d) v += u;
        }
        if ((t & 31) == 31) wsum[t >> 5] = v;
        __syncthreads();
        if (t == 0) {
            int run = 0;
#pragma unroll
            for (int i = 0; i < 8; i++) { woff[i] = run; run += wsum[i]; }
        }
        __syncthreads();
        g_off[t * 128 + b] = v + woff[t >> 5] - c;   // exclusive
        return;
    }

    // losses block
    {
        int e = t >> 2, q = t & 3;
        int csum = 0;
        for (int blk = q * 64; blk < q * 64 + 64; blk++)
            csum += g_counts[blk * 128 + e];          // top-1 bins are 0..63
        float msum = 0.f;
        for (int blk = q * 32; blk < q * 32 + 32; blk++)
            msum += g_mepart[blk * 64 + e];
        ired[t] = csum;
        fred[t] = msum;
    }
    __syncthreads();
    float a = 0.f;
    if (t < 64) {
        float me = (fred[4*t] + fred[4*t+1] + fred[4*t+2] + fred[4*t+3]) * (1.f / (float)N_TOK);
        float ce = (float)(ired[4*t] + ired[4*t+1] + ired[4*t+2] + ired[4*t+3]) * (1.f / (float)N_TOK);
        a = (float)E_DIM * me * ce;
    }
    __syncthreads();
    fred[t] = (t < 64) ? a : 0.f;
    __syncthreads();
    for (int s = 128; s > 0; s >>= 1) {
        if (t < s) fred[t] += fred[t + s];
        __syncthreads();
    }
    if (t == 0) out[AUX_OFF] = fred[0];
    __syncthreads();

    fred[t] = (t < NCTA_MAIN) ? g_zpart[t] : 0.f;
    __syncthreads();
    for (int s = 128; s > 0; s >>= 1) {
        if (t < s) fred[t] += fred[t + s];
        __syncthreads();
    }
    if (t == 0) out[Z_OFF] = fred[0] * (1.f / ((float)N_TOK * (float)E_DIM));
}

// ---------------- K3: dense per-token writes (no zero pass, no sync) -------
// 2048 CTAs x 256 threads; warp per token; lane owns experts 2*lane, 2*lane+1.
__global__ __launch_bounds__(256) void k_out(float* __restrict__ out) {
    const int wid  = (blockIdx.x << 3) + (threadIdx.x >> 5);  // token 0..16383
    const int lane = threadIdx.x & 31;
    const int n = wid;

    uint32_t ii = g_t2i[n];
    int e1 = ii & 0xff, e2 = (ii >> 8) & 0xff;
    uint32_t rr = g_rank[n];
    float2 vv = g_t2v[n];
    int blk64 = n >> 6;

    int pos0 = g_off[blk64 * 128 + e1]      + (int)(rr & 0xffff);
    int pos1 = g_off[blk64 * 128 + 64 + e2] + (int)(rr >> 16);
    bool k0 = pos0 < CAP, k1 = pos1 < CAP;

    int ea = 2 * lane, ebx = 2 * lane + 1;
    float4 d = make_float4(0.f, 0.f, 0.f, 0.f);
    float4 c = make_float4(0.f, 0.f, 0.f, 0.f);
    if (k0 && e1 == ea)  { d.x = 1.f; c.x = vv.x; }
    if (k1 && e2 == ea)  { d.y = 1.f; c.y = vv.y; }
    if (k0 && e1 == ebx) { d.z = 1.f; c.z = vv.x; }
    if (k1 && e2 == ebx) { d.w = 1.f; c.w = vv.y; }

    size_t base = (size_t)n * 128 + lane * 4;
    *(float4*)(out + DISP_OFF + base) = d;
    *(float4*)(out + COMB_OFF + base) = c;
}

// ---------------- entry ----------------
extern "C" void kernel_launch(void* const* d_in, const int* in_sizes, int n_in,
                              void* d_out, int out_size) {
    const float* x = (const float*)d_in[0];   // [16384, 2048]
    const float* W = (const float*)d_in[1];   // [64, 2048]
    float* out = (float*)d_out;

    cudaFuncSetAttribute(k_main, cudaFuncAttributeMaxDynamicSharedMemorySize, SMEM_DYN);

    k_wsplit<<<(E_DIM * C_DIM) / 256, 256>>>(W);
    k_main<<<NCTA_MAIN, NTHREADS, SMEM_DYN>>>(x);
    k_scan<<<129, 256>>>(out);
    k_out<<<N_TOK / 8, 256>>>(out);
}